// round 8
// baseline (speedup 1.0000x reference)
#include <cuda_runtime.h>

// out[b,s,f,o] = sum_{t,k,c} x[b, s+t-2, f*(k+1), c] * W[t,k,c,o],  f*(k+1) < F
// x [4,1024,512,4] f32, W [5,4,4,4] f32, out [4,1024,512,4] f32.
//
// R8: c-packed FFMA2 + __constant__ weights + ring buffer (R6/R7 core), plus:
//     - 8 s per thread: two U=4 chunks share the ring across the boundary
//       (gathers 16 -> 12 per 8 outputs, acc stays 32 regs)
//     - block-uniform interior/boundary split: interior blocks (126/128) run
//       with zero boundary predicates/selects on gather loads.

#define B_  4
#define S_  1024
#define F_  512
#define U_  4          // outputs per chunk
#define NC  2          // chunks per thread -> 8 s per thread
#define NT  5
#define NK  4
#define TPB 256

typedef unsigned long long u64;

// Wc2[(k*NT+t)*4 + o] : floats (c0,c1,c2,c3) -> .x=(c0,c1) .y=(c2,c3)
__constant__ ulonglong2 Wc2[NK * NT * 4];
__device__ float Wt_scratch[NT * NK * 16];

__global__ void transpose_w_kernel(const float* __restrict__ W)
{
    int i = threadIdx.x;
    if (i < NT * NK * 16) {
        int o = i & 3, c = (i >> 2) & 3, k = (i >> 4) & 3, t = i >> 6;
        Wt_scratch[((k * NT + t) * 4 + o) * 4 + c] = W[i];
    }
}

__device__ __forceinline__ u64 fma2(u64 a, u64 b, u64 c) {
    u64 d;
    asm("fma.rn.f32x2 %0, %1, %2, %3;" : "=l"(d) : "l"(a), "l"(b), "l"(c));
    return d;
}

template <bool GUARD>
__device__ __forceinline__ void run_cols(
    int f, int s0, const ulonglong2* __restrict__ xb,
    float4* __restrict__ o4)
{
    for (int k = 0; k < NK; ++k) {
        int fk = f * (k + 1);
        if (fk >= F_) break;                      // monotone in k, warp-coherent
        const ulonglong2* __restrict__ col = xb + fk;

        // absolute row m corresponds to sp = s0 + m - 2; ring slot = m & 3
        ulonglong2 r[4];
#pragma unroll
        for (int m = 0; m < 4; ++m) {             // preload rows 0..3
            int sp = s0 + m - 2;
            if (GUARD)
                r[m] = (sp >= 0 && sp < S_) ? col[(size_t)sp * F_]
                                            : make_ulonglong2(0ull, 0ull);
            else
                r[m] = col[(size_t)sp * F_];
        }

#pragma unroll
        for (int c = 0; c < NC; ++c) {
            u64 acc[U_][4];
#pragma unroll
            for (int j = 0; j < U_; ++j)
#pragma unroll
                for (int o = 0; o < 4; ++o) acc[j][o] = 0ull;

#pragma unroll
            for (int t = 0; t < NT; ++t) {
                ulonglong2 w0 = Wc2[(k * NT + t) * 4 + 0];
                ulonglong2 w1 = Wc2[(k * NT + t) * 4 + 1];
                ulonglong2 w2 = Wc2[(k * NT + t) * 4 + 2];
                ulonglong2 w3 = Wc2[(k * NT + t) * 4 + 3];
#pragma unroll
                for (int j = 0; j < U_; ++j) {
                    ulonglong2 rv = r[(t + j) & 3];   // abs row 4c+j+t
                    acc[j][0] = fma2(rv.x, w0.x, acc[j][0]);
                    acc[j][1] = fma2(rv.x, w1.x, acc[j][1]);
                    acc[j][2] = fma2(rv.x, w2.x, acc[j][2]);
                    acc[j][3] = fma2(rv.x, w3.x, acc[j][3]);
                    acc[j][0] = fma2(rv.y, w0.y, acc[j][0]);
                    acc[j][1] = fma2(rv.y, w1.y, acc[j][1]);
                    acc[j][2] = fma2(rv.y, w2.y, acc[j][2]);
                    acc[j][3] = fma2(rv.y, w3.y, acc[j][3]);
                }
                if (t < NT - 1) {                 // load abs row 4c+t+4
                    int sp = s0 + 4 * c + t + 2;
                    if (GUARD)
                        r[t & 3] = (sp >= 0 && sp < S_) ? col[(size_t)sp * F_]
                                                        : make_ulonglong2(0ull, 0ull);
                    else
                        r[t & 3] = col[(size_t)sp * F_];
                }
            }

            // fold c-halves, accumulate into output (k accumulates via +=)
#pragma unroll
            for (int j = 0; j < U_; ++j) {
                float2 a0 = reinterpret_cast<float2&>(acc[j][0]);
                float2 a1 = reinterpret_cast<float2&>(acc[j][1]);
                float2 a2 = reinterpret_cast<float2&>(acc[j][2]);
                float2 a3 = reinterpret_cast<float2&>(acc[j][3]);
                float4 v = make_float4(a0.x + a0.y, a1.x + a1.y,
                                       a2.x + a2.y, a3.x + a3.y);
                size_t oi = (size_t)(c * U_ + j) * F_;
                if (k == 0) o4[oi] = v;
                else {
                    float4 p = o4[oi];
                    o4[oi] = make_float4(p.x + v.x, p.y + v.y,
                                         p.z + v.z, p.w + v.w);
                }
            }
        }
    }
}

__global__ __launch_bounds__(TPB, 4) void harm_conv_kernel(
    const float* __restrict__ x,
    float* __restrict__ out)
{
    int gid = blockIdx.x * TPB + threadIdx.x;

    // f-chunk interleave for block-duration balance (4 heavy + 4 light warps)
    int lane = gid & 31;
    int w    = (gid >> 5) & 15;
    int wpp  = ((w & 7) << 1) | (w >> 3);
    int f    = (wpp << 5) | lane;

    int sb = (gid >> 9) & (S_ / (U_ * NC) - 1);   // 0..127, block-uniform
    int b  = gid >> 16;
    int s0 = sb * (U_ * NC);

    const ulonglong2* __restrict__ xb =
        reinterpret_cast<const ulonglong2*>(x) + (size_t)b * S_ * F_;
    float4* __restrict__ o4 =
        reinterpret_cast<float4*>(out) + ((size_t)(b * S_ + s0)) * F_ + f;

    if (s0 >= 2 && s0 + U_ * NC + 1 < S_)         // block-uniform branch
        run_cols<false>(f, s0, xb, o4);
    else
        run_cols<true>(f, s0, xb, o4);
}

extern "C" void kernel_launch(void* const* d_in, const int* in_sizes, int n_in,
                              void* d_out, int out_size)
{
    const float* x = (const float*)d_in[0];
    const float* W = (const float*)d_in[1];
    float* out = (float*)d_out;

    transpose_w_kernel<<<1, NT * NK * 16>>>(W);

    void* wt_dev = nullptr;
    cudaGetSymbolAddress(&wt_dev, Wt_scratch);
    cudaMemcpyToSymbolAsync(Wc2, wt_dev, NT * NK * 16 * sizeof(float), 0,
                            cudaMemcpyDeviceToDevice, 0);

    int total = B_ * (S_ / (U_ * NC)) * F_;       // one thread per (b, 8s, f)
    harm_conv_kernel<<<total / TPB, TPB>>>(x, out);
}

// round 9
// speedup vs baseline: 3.0987x; 3.0987x over previous
#include <cuda_runtime.h>

// out[b,s,f,o] = sum_{t,k,c} x[b, s+t-2, f*(k+1), c] * W[t,k,c,o],  f*(k+1) < F
// x [4,1024,512,4] f32, W [5,4,4,4] f32, out [4,1024,512,4] f32.
//
// R9: register-resident acc across k (R6) + 8-row upfront buffer per k
//     (MLP=8, immediate-offset LDGs) + __constant__ weights + guard-free
//     interior blocks + f-interleave. 84-reg ceiling (3 blocks/SM).

#define B_  4
#define S_  1024
#define F_  512
#define U_  4
#define NT  5
#define NK  4
#define TPB 256

typedef unsigned long long u64;

// Wc2[(k*NT+t)*4 + o] : floats (c0,c1,c2,c3) -> .x=(c0,c1) .y=(c2,c3)
__constant__ ulonglong2 Wc2[NK * NT * 4];
__device__ float Wt_scratch[NT * NK * 16];

__global__ void transpose_w_kernel(const float* __restrict__ W)
{
    int i = threadIdx.x;
    if (i < NT * NK * 16) {
        int o = i & 3, c = (i >> 2) & 3, k = (i >> 4) & 3, t = i >> 6;
        Wt_scratch[((k * NT + t) * 4 + o) * 4 + c] = W[i];
    }
}

__device__ __forceinline__ u64 fma2(u64 a, u64 b, u64 c) {
    u64 d;
    asm("fma.rn.f32x2 %0, %1, %2, %3;" : "=l"(d) : "l"(a), "l"(b), "l"(c));
    return d;
}

template <bool GUARD>
__device__ __forceinline__ void body(
    int f, int s0, const ulonglong2* __restrict__ xb, u64 acc[U_][4])
{
    for (int k = 0; k < NK; ++k) {
        int fk = f * (k + 1);
        if (fk >= F_) break;                      // monotone in k, warp-coherent
        // single base; row offsets are compile-time immediates (MLP=8)
        const ulonglong2* __restrict__ base = xb + fk + (size_t)(s0 - 2) * F_;

        ulonglong2 r[U_ + 4];
#pragma unroll
        for (int i = 0; i < U_ + 4; ++i) {
            if (GUARD) {
                int sp = s0 + i - 2;
                r[i] = (sp >= 0 && sp < S_) ? base[(size_t)i * F_]
                                            : make_ulonglong2(0ull, 0ull);
            } else {
                r[i] = base[(size_t)i * F_];
            }
        }

#pragma unroll
        for (int t = 0; t < NT; ++t) {
            ulonglong2 w0 = Wc2[(k * NT + t) * 4 + 0];
            ulonglong2 w1 = Wc2[(k * NT + t) * 4 + 1];
            ulonglong2 w2 = Wc2[(k * NT + t) * 4 + 2];
            ulonglong2 w3 = Wc2[(k * NT + t) * 4 + 3];
#pragma unroll
            for (int j = 0; j < U_; ++j) {
                ulonglong2 rv = r[j + t];
                acc[j][0] = fma2(rv.x, w0.x, acc[j][0]);
                acc[j][1] = fma2(rv.x, w1.x, acc[j][1]);
                acc[j][2] = fma2(rv.x, w2.x, acc[j][2]);
                acc[j][3] = fma2(rv.x, w3.x, acc[j][3]);
                acc[j][0] = fma2(rv.y, w0.y, acc[j][0]);
                acc[j][1] = fma2(rv.y, w1.y, acc[j][1]);
                acc[j][2] = fma2(rv.y, w2.y, acc[j][2]);
                acc[j][3] = fma2(rv.y, w3.y, acc[j][3]);
            }
        }
    }
}

__global__ __launch_bounds__(TPB, 3) void harm_conv_kernel(
    const float* __restrict__ x,
    float* __restrict__ out)
{
    int gid = blockIdx.x * TPB + threadIdx.x;

    // f-chunk interleave: block gets 4 heavy + 4 light warps (duration balance)
    int lane = gid & 31;
    int w    = (gid >> 5) & 15;
    int wpp  = ((w & 7) << 1) | (w >> 3);
    int f    = (wpp << 5) | lane;

    int sb = (gid >> 9) & (S_ / U_ - 1);          // block-uniform
    int b  = gid >> 17;
    int s0 = sb * U_;

    const ulonglong2* __restrict__ xb =
        reinterpret_cast<const ulonglong2*>(x) + (size_t)b * S_ * F_;

    u64 acc[U_][4];
#pragma unroll
    for (int j = 0; j < U_; ++j)
#pragma unroll
        for (int o = 0; o < 4; ++o) acc[j][o] = 0ull;

    if (sb > 0 && sb < S_ / U_ - 1)               // block-uniform branch
        body<false>(f, s0, xb, acc);
    else
        body<true>(f, s0, xb, acc);

    // epilogue: fold the two c-halves per output
    float4* __restrict__ o4 =
        reinterpret_cast<float4*>(out) + ((size_t)(b * S_ + s0)) * F_ + f;
#pragma unroll
    for (int j = 0; j < U_; ++j) {
        float2 a0 = reinterpret_cast<float2&>(acc[j][0]);
        float2 a1 = reinterpret_cast<float2&>(acc[j][1]);
        float2 a2 = reinterpret_cast<float2&>(acc[j][2]);
        float2 a3 = reinterpret_cast<float2&>(acc[j][3]);
        o4[(size_t)j * F_] = make_float4(a0.x + a0.y, a1.x + a1.y,
                                         a2.x + a2.y, a3.x + a3.y);
    }
}

extern "C" void kernel_launch(void* const* d_in, const int* in_sizes, int n_in,
                              void* d_out, int out_size)
{
    const float* x = (const float*)d_in[0];
    const float* W = (const float*)d_in[1];
    float* out = (float*)d_out;

    transpose_w_kernel<<<1, NT * NK * 16>>>(W);

    void* wt_dev = nullptr;
    cudaGetSymbolAddress(&wt_dev, Wt_scratch);
    cudaMemcpyToSymbolAsync(Wc2, wt_dev, NT * NK * 16 * sizeof(float), 0,
                            cudaMemcpyDeviceToDevice, 0);

    int total = B_ * (S_ / U_) * F_;              // one thread per (b, 4s, f)
    harm_conv_kernel<<<total / TPB, TPB>>>(x, out);
}